// round 1
// baseline (speedup 1.0000x reference)
#include <cuda_runtime.h>
#include <cuda_bf16.h>
#include <cstdint>

// ---------------------------------------------------------------------------
// Layer_GCN: out = A @ (X @ W) + bias, A in COO (edge_src -> edge_dst, weight)
// N=100000 nodes, E=3200000 edges, D_IN=D_OUT=256, all fp32.
//
// Plan:
//   k0: out[i] = bias[i % 256]
//   k1: g_support = X @ W   (fp32 tiled GEMM, 64x64x32 tiles, 4x4 per thread)
//   k2: per-edge warp scatter: red.global.add.v4.f32 of support[src]*w into out[dst]
// ---------------------------------------------------------------------------

#define D_DIM 256
#define MAX_NODES 100000

// scratch for support = X @ W  (static device global: allocation-free)
__device__ float g_support[(size_t)MAX_NODES * D_DIM];

// ---------------------------------------------------------------------------
// k0: init out with bias broadcast (vectorized)
// ---------------------------------------------------------------------------
__global__ void init_out_kernel(float4* __restrict__ out4,
                                const float4* __restrict__ bias4,
                                int n4) {
    int i = blockIdx.x * blockDim.x + threadIdx.x;
    if (i < n4) {
        out4[i] = bias4[i & 63];   // 256 floats = 64 float4 per row
    }
}

// ---------------------------------------------------------------------------
// k1: support = X @ W   (N x 256) @ (256 x 256), fp32
// ---------------------------------------------------------------------------
#define BM 64
#define BN 64
#define BK 32

__global__ __launch_bounds__(256) void gemm_kernel(const float* __restrict__ X,
                                                   const float* __restrict__ W,
                                                   float* __restrict__ S,
                                                   int n_rows) {
    __shared__ float As[BK][BM + 4];   // [k][m]
    __shared__ float Bs[BK][BN + 4];   // [k][n]

    const int bm = blockIdx.x * BM;
    const int bn = blockIdx.y * BN;
    const int tid = threadIdx.x;
    const int tx = tid & 15;    // col group (0..15) -> 4 cols
    const int ty = tid >> 4;    // row group (0..15) -> 4 rows

    float acc[4][4] = {};

    for (int k0 = 0; k0 < D_DIM; k0 += BK) {
        // load A tile: BM x BK = 2048 floats = 512 float4, 2 per thread
        #pragma unroll
        for (int i = 0; i < 2; i++) {
            int idx = tid + i * 256;            // 0..511
            int m   = idx >> 3;                 // 8 float4 per row (BK/4)
            int kq  = (idx & 7) * 4;
            int row = bm + m;
            float4 v = make_float4(0.f, 0.f, 0.f, 0.f);
            if (row < n_rows)
                v = *(const float4*)(X + (size_t)row * D_DIM + k0 + kq);
            As[kq + 0][m] = v.x;
            As[kq + 1][m] = v.y;
            As[kq + 2][m] = v.z;
            As[kq + 3][m] = v.w;
        }
        // load B tile: BK x BN = 2048 floats, 2 float4 per thread
        #pragma unroll
        for (int i = 0; i < 2; i++) {
            int idx = tid + i * 256;
            int k   = idx >> 4;                 // 16 float4 per row (BN/4)
            int nq  = (idx & 15) * 4;
            float4 v = *(const float4*)(W + (size_t)(k0 + k) * D_DIM + bn + nq);
            *(float4*)&Bs[k][nq] = v;
        }
        __syncthreads();

        #pragma unroll
        for (int k = 0; k < BK; k++) {
            float a[4], b[4];
            #pragma unroll
            for (int i = 0; i < 4; i++) a[i] = As[k][ty * 4 + i];
            #pragma unroll
            for (int j = 0; j < 4; j++) b[j] = Bs[k][tx * 4 + j];
            #pragma unroll
            for (int i = 0; i < 4; i++)
                #pragma unroll
                for (int j = 0; j < 4; j++)
                    acc[i][j] += a[i] * b[j];
        }
        __syncthreads();
    }

    #pragma unroll
    for (int i = 0; i < 4; i++) {
        int row = bm + ty * 4 + i;
        if (row < n_rows) {
            float4 v = make_float4(acc[i][0], acc[i][1], acc[i][2], acc[i][3]);
            *(float4*)(S + (size_t)row * D_DIM + bn + tx * 4) = v;
        }
    }
}

// ---------------------------------------------------------------------------
// k2: edge scatter. One warp per edge: 32 lanes x 2 float4 = 256 floats.
// red.global.add.v4.f32 = vectorized no-return atomic add (sm_90+).
// ---------------------------------------------------------------------------
__global__ __launch_bounds__(256) void scatter_kernel(const float* __restrict__ S,
                                                      const int* __restrict__ esrc,
                                                      const int* __restrict__ edst,
                                                      const float* __restrict__ ew,
                                                      float* __restrict__ out,
                                                      int n_edges) {
    int e = blockIdx.x * 8 + (threadIdx.x >> 5);
    if (e >= n_edges) return;
    int lane = threadIdx.x & 31;

    int s = esrc[e];
    int d = edst[e];
    float wt = ew[e];

    const float4* srow = (const float4*)(S + (size_t)s * D_DIM);
    float4*       drow = (float4*)(out + (size_t)d * D_DIM);

    #pragma unroll
    for (int i = 0; i < 2; i++) {
        float4 v = srow[lane + 32 * i];
        v.x *= wt; v.y *= wt; v.z *= wt; v.w *= wt;
        asm volatile("red.global.add.v4.f32 [%0], {%1, %2, %3, %4};"
                     :: "l"(drow + lane + 32 * i),
                        "f"(v.x), "f"(v.y), "f"(v.z), "f"(v.w)
                     : "memory");
    }
}

// ---------------------------------------------------------------------------
// launch
// inputs (metadata order): x[N*256], edge_src[E], edge_dst[E], edge_weight[E],
//                          weight[256*256], bias[256]
// ---------------------------------------------------------------------------
extern "C" void kernel_launch(void* const* d_in, const int* in_sizes, int n_in,
                              void* d_out, int out_size) {
    const float* x    = (const float*)d_in[0];
    const int*   esrc = (const int*)d_in[1];
    const int*   edst = (const int*)d_in[2];
    const float* ew   = (const float*)d_in[3];
    const float* w    = (const float*)d_in[4];
    const float* bias = (const float*)d_in[5];
    float* out = (float*)d_out;

    const int n_nodes = in_sizes[0] / D_DIM;
    const int n_edges = in_sizes[1];

    float* support;
    cudaGetSymbolAddress((void**)&support, g_support);

    // k0: out = bias (broadcast)
    {
        int n4 = out_size / 4;
        int threads = 256;
        int blocks = (n4 + threads - 1) / threads;
        init_out_kernel<<<blocks, threads>>>((float4*)out, (const float4*)bias, n4);
    }

    // k1: support = X @ W
    {
        dim3 grid((n_nodes + BM - 1) / BM, D_DIM / BN);
        gemm_kernel<<<grid, 256>>>(x, w, support, n_nodes);
    }

    // k2: scatter edges (one warp per edge, 8 warps per block)
    {
        int blocks = (n_edges + 7) / 8;
        scatter_kernel<<<blocks, 256>>>(support, esrc, edst, ew, out, n_edges);
    }
}

// round 2
// speedup vs baseline: 1.8955x; 1.8955x over previous
#include <cuda_runtime.h>
#include <cuda_bf16.h>
#include <cstdint>

// ---------------------------------------------------------------------------
// Layer_GCN: out = A @ (X @ W) + bias, A in COO (edge_src -> edge_dst, weight)
// N=100000, E=3200000, D=256, fp32.
//
// Pipeline (all on one stream, graph-capturable, allocation-free):
//   k_zero  : cnt[] = 0
//   k_hist  : cnt[dst]++                    (REDG on 100k counters)
//   k_scan1 : per-block exclusive scan of cnt -> row, block sums -> aux
//   k_scan2 : serial exclusive scan of aux
//   k_add   : row += aux[block]; cursor = row
//   k_fill  : pos = atomicAdd(cursor[dst]); edges_sorted[pos] = (src, w)
//   k_gemm  : support = X @ W               (fp32, 128x64x16 tiles, 8x4 micro)
//   k_accum : one warp per dst node: acc += w * support[src]; out = acc + bias
// ---------------------------------------------------------------------------

#define D_DIM     256
#define MAX_NODES 100000
#define MAX_EDGES 3200000

#define SCAN_BLK  2048                 // elements per scan block (1024 thr x 2)
#define N_SCANBLK ((MAX_NODES + SCAN_BLK - 1) / SCAN_BLK)   // 49

__device__ float g_support[(size_t)MAX_NODES * D_DIM];
__device__ int2  g_edges[MAX_EDGES];          // (src, weight bits), dst-sorted
__device__ int   g_cnt[MAX_NODES];
__device__ int   g_row[MAX_NODES];
__device__ int   g_cursor[MAX_NODES];
__device__ int   g_aux[N_SCANBLK + 1];

// ---------------------------------------------------------------------------
__global__ void zero_kernel(int* __restrict__ p, int n) {
    int i = blockIdx.x * blockDim.x + threadIdx.x;
    if (i < n) p[i] = 0;
}

__global__ void hist_kernel(const int* __restrict__ edst, int* __restrict__ cnt,
                            int n_edges) {
    int e = blockIdx.x * blockDim.x + threadIdx.x;
    if (e < n_edges) atomicAdd(&cnt[edst[e]], 1);
}

// per-block exclusive scan (2048 elems / block), block totals to aux
__global__ __launch_bounds__(1024) void scan1_kernel(const int* __restrict__ cnt,
                                                     int* __restrict__ row,
                                                     int* __restrict__ aux,
                                                     int n) {
    __shared__ int sdata[1024];
    int t  = threadIdx.x;
    int i0 = blockIdx.x * SCAN_BLK + t * 2;

    int c0 = (i0     < n) ? cnt[i0]     : 0;
    int c1 = (i0 + 1 < n) ? cnt[i0 + 1] : 0;
    int tsum = c0 + c1;

    sdata[t] = tsum;
    __syncthreads();
    #pragma unroll
    for (int off = 1; off < 1024; off <<= 1) {
        int v = (t >= off) ? sdata[t - off] : 0;
        __syncthreads();
        sdata[t] += v;
        __syncthreads();
    }
    int excl = sdata[t] - tsum;

    if (i0     < n) row[i0]     = excl;
    if (i0 + 1 < n) row[i0 + 1] = excl + c0;
    if (t == 1023) aux[blockIdx.x] = sdata[t];
}

__global__ void scan2_kernel(int* __restrict__ aux, int nb) {
    if (threadIdx.x == 0 && blockIdx.x == 0) {
        int run = 0;
        for (int i = 0; i < nb; i++) { int v = aux[i]; aux[i] = run; run += v; }
    }
}

__global__ __launch_bounds__(1024) void add_kernel(int* __restrict__ row,
                                                   int* __restrict__ cursor,
                                                   const int* __restrict__ aux,
                                                   int n) {
    int off = aux[blockIdx.x];
    int i0  = blockIdx.x * SCAN_BLK + threadIdx.x * 2;
    if (i0 < n)     { int v = row[i0]     + off; row[i0]     = v; cursor[i0]     = v; }
    if (i0 + 1 < n) { int v = row[i0 + 1] + off; row[i0 + 1] = v; cursor[i0 + 1] = v; }
}

__global__ void fill_kernel(const int* __restrict__ esrc,
                            const int* __restrict__ edst,
                            const float* __restrict__ ew,
                            int* __restrict__ cursor,
                            int2* __restrict__ edges,
                            int n_edges) {
    int e = blockIdx.x * blockDim.x + threadIdx.x;
    if (e < n_edges) {
        int pos = atomicAdd(&cursor[edst[e]], 1);
        edges[pos] = make_int2(esrc[e], __float_as_int(ew[e]));
    }
}

// ---------------------------------------------------------------------------
// GEMM: support = X @ W.  128x64 tile, BK=16, 256 threads, 8x4 micro-tile.
// ---------------------------------------------------------------------------
#define BM 128
#define BN 64
#define BK 16

__global__ __launch_bounds__(256) void gemm_kernel(const float* __restrict__ X,
                                                   const float* __restrict__ W,
                                                   float* __restrict__ S,
                                                   int n_rows) {
    __shared__ float As[BK][BM + 4];
    __shared__ float Bs[BK][BN + 4];

    const int bm  = blockIdx.x * BM;
    const int bn  = blockIdx.y * BN;
    const int tid = threadIdx.x;
    const int tx  = tid & 15;    // 4 cols each
    const int ty  = tid >> 4;    // 8 rows each

    float acc[8][4] = {};

    for (int k0 = 0; k0 < D_DIM; k0 += BK) {
        // A tile: 128 x 16 = 512 float4, 2 per thread
        #pragma unroll
        for (int i = 0; i < 2; i++) {
            int idx = tid + i * 256;
            int m   = idx >> 2;             // 4 float4 per row
            int kq  = (idx & 3) * 4;
            int r   = bm + m;
            float4 v = make_float4(0.f, 0.f, 0.f, 0.f);
            if (r < n_rows)
                v = *(const float4*)(X + (size_t)r * D_DIM + k0 + kq);
            As[kq + 0][m] = v.x;
            As[kq + 1][m] = v.y;
            As[kq + 2][m] = v.z;
            As[kq + 3][m] = v.w;
        }
        // B tile: 16 x 64 = 256 float4, 1 per thread
        {
            int k  = tid >> 4;
            int nq = (tid & 15) * 4;
            float4 v = *(const float4*)(W + (size_t)(k0 + k) * D_DIM + bn + nq);
            *(float4*)&Bs[k][nq] = v;
        }
        __syncthreads();

        #pragma unroll
        for (int k = 0; k < BK; k++) {
            float a[8], b[4];
            #pragma unroll
            for (int i = 0; i < 8; i++) a[i] = As[k][ty * 8 + i];
            #pragma unroll
            for (int j = 0; j < 4; j++) b[j] = Bs[k][tx * 4 + j];
            #pragma unroll
            for (int i = 0; i < 8; i++)
                #pragma unroll
                for (int j = 0; j < 4; j++)
                    acc[i][j] += a[i] * b[j];
        }
        __syncthreads();
    }

    #pragma unroll
    for (int i = 0; i < 8; i++) {
        int r = bm + ty * 8 + i;
        if (r < n_rows) {
            float4 v = make_float4(acc[i][0], acc[i][1], acc[i][2], acc[i][3]);
            *(float4*)(S + (size_t)r * D_DIM + bn + tx * 4) = v;
        }
    }
}

// ---------------------------------------------------------------------------
// accum: one warp per dst node. No atomics. out = sum(w * S[src]) + bias.
// ---------------------------------------------------------------------------
__global__ __launch_bounds__(256) void accum_kernel(const float* __restrict__ S,
                                                    const int2* __restrict__ edges,
                                                    const int* __restrict__ row,
                                                    const int* __restrict__ cnt,
                                                    const float4* __restrict__ bias4,
                                                    float4* __restrict__ out4,
                                                    int n_nodes) {
    int node = blockIdx.x * 8 + (threadIdx.x >> 5);
    if (node >= n_nodes) return;
    int lane = threadIdx.x & 31;

    int start = row[node];
    int deg   = cnt[node];

    float4 acc0 = make_float4(0.f, 0.f, 0.f, 0.f);
    float4 acc1 = make_float4(0.f, 0.f, 0.f, 0.f);

    for (int base = 0; base < deg; base += 32) {
        int m = min(32, deg - base);
        int2 ed = make_int2(0, 0);
        if (lane < m) ed = edges[start + base + lane];

        for (int j = 0; j < m; j++) {
            int   s  = __shfl_sync(0xffffffffu, ed.x, j);
            float wj = __int_as_float(__shfl_sync(0xffffffffu, ed.y, j));
            const float4* srow = (const float4*)(S + (size_t)s * D_DIM);
            float4 v0 = srow[lane];
            float4 v1 = srow[lane + 32];
            acc0.x += wj * v0.x; acc0.y += wj * v0.y;
            acc0.z += wj * v0.z; acc0.w += wj * v0.w;
            acc1.x += wj * v1.x; acc1.y += wj * v1.y;
            acc1.z += wj * v1.z; acc1.w += wj * v1.w;
        }
    }

    float4 b0 = bias4[lane];
    float4 b1 = bias4[lane + 32];
    acc0.x += b0.x; acc0.y += b0.y; acc0.z += b0.z; acc0.w += b0.w;
    acc1.x += b1.x; acc1.y += b1.y; acc1.z += b1.z; acc1.w += b1.w;

    float4* drow = out4 + (size_t)node * (D_DIM / 4);
    __stcs(drow + lane,      acc0);   // streaming store: don't pollute L2
    __stcs(drow + lane + 32, acc1);
}

// ---------------------------------------------------------------------------
extern "C" void kernel_launch(void* const* d_in, const int* in_sizes, int n_in,
                              void* d_out, int out_size) {
    const float* x    = (const float*)d_in[0];
    const int*   esrc = (const int*)d_in[1];
    const int*   edst = (const int*)d_in[2];
    const float* ew   = (const float*)d_in[3];
    const float* w    = (const float*)d_in[4];
    const float* bias = (const float*)d_in[5];
    float* out = (float*)d_out;

    const int n_nodes = in_sizes[0] / D_DIM;
    const int n_edges = in_sizes[1];

    float* S;     cudaGetSymbolAddress((void**)&S, g_support);
    int2*  edges; cudaGetSymbolAddress((void**)&edges, g_edges);
    int*   cnt;   cudaGetSymbolAddress((void**)&cnt, g_cnt);
    int*   rowp;  cudaGetSymbolAddress((void**)&rowp, g_row);
    int*   cur;   cudaGetSymbolAddress((void**)&cur, g_cursor);
    int*   aux;   cudaGetSymbolAddress((void**)&aux, g_aux);

    const int nb_scan = (n_nodes + SCAN_BLK - 1) / SCAN_BLK;

    // CSR build
    zero_kernel<<<(n_nodes + 1023) / 1024, 1024>>>(cnt, n_nodes);
    hist_kernel<<<(n_edges + 511) / 512, 512>>>(edst, cnt, n_edges);
    scan1_kernel<<<nb_scan, 1024>>>(cnt, rowp, aux, n_nodes);
    scan2_kernel<<<1, 32>>>(aux, nb_scan);
    add_kernel<<<nb_scan, 1024>>>(rowp, cur, aux, n_nodes);
    fill_kernel<<<(n_edges + 511) / 512, 512>>>(esrc, edst, ew, cur, edges, n_edges);

    // support = X @ W
    {
        dim3 grid((n_nodes + BM - 1) / BM, D_DIM / BN);
        gemm_kernel<<<grid, 256>>>(x, w, S, n_nodes);
    }

    // out = A @ support + bias (no atomics)
    accum_kernel<<<(n_nodes + 7) / 8, 256>>>(S, edges, rowp, cnt,
                                             (const float4*)bias,
                                             (float4*)out, n_nodes);
}